// round 13
// baseline (speedup 1.0000x reference)
#include <cuda_runtime.h>

#define BH     32
#define LSEQ   4096
#define D      128
#define C      32
#define NCHUNK 128
#define NSPLIT 4

typedef unsigned long long ull;

// Scratch (device globals are the allowed scratch mechanism)
// g_qt / g_wt are d-pair-interleaved ull arrays: ull idx = chunkbase*64 + d2*32 + c
//   value = ( {q,w}[2*d2][c] , {q,w}[2*d2+1][c] )
__device__ __align__(16) float g_qt[(size_t)BH * LSEQ * D];
__device__ __align__(16) float g_kn[(size_t)BH * LSEQ * D];   // row-major normalized k
__device__ __align__(16) float g_u [(size_t)BH * LSEQ * D];   // u0 (row-major)
__device__ __align__(16) float g_wt[(size_t)BH * LSEQ * D];
__device__ __align__(16) float g_attn[(size_t)BH * NCHUNK * C * C];  // attn^T: [t][c]

// ---------------------------------------------------------------------------
// f32x2 packed helpers
// ---------------------------------------------------------------------------
__device__ __forceinline__ void fma2(ull& acc, ull a, ull b) {
    asm("fma.rn.f32x2 %0, %1, %2, %0;" : "+l"(acc) : "l"(a), "l"(b));
}
__device__ __forceinline__ ull packdup(float s) {
    ull r;
    asm("mov.b64 %0, {%1, %1};" : "=l"(r) : "r"(__float_as_uint(s)));
    return r;
}
__device__ __forceinline__ ull pack2(float lo, float hi) {
    ull r;
    asm("mov.b64 %0, {%1, %2};" : "=l"(r) : "r"(__float_as_uint(lo)), "r"(__float_as_uint(hi)));
    return r;
}
__device__ __forceinline__ void unpack2(ull v, float& lo, float& hi) {
    unsigned a, b;
    asm("mov.b64 {%0, %1}, %2;" : "=r"(a), "=r"(b) : "l"(v));
    lo = __uint_as_float(a); hi = __uint_as_float(b);
}
__device__ __forceinline__ float hadd2(ull v) {
    float lo, hi; unpack2(v, lo, hi); return lo + hi;
}

// ---------------------------------------------------------------------------
// Kernel 1 (fused norm + chunk). 4096 blocks, 128 threads.
// R11 structure (scalar Phase 4 — faster than the R12 f32x2 variant),
// with pair-packed q/w drains for the scan's layout.
// ---------------------------------------------------------------------------
__global__ void chunk_kernel(const float* __restrict__ q,
                             const float* __restrict__ k,
                             const float* __restrict__ v,
                             const float* __restrict__ beta) {
    __shared__ float knT[128 * 33];
    __shared__ float qnT[128 * 33];
    __shared__ float A[32 * 33];
    __shared__ float beta_s[32];

    int tid = threadIdx.x;
    int lane = tid & 31, wrp = tid >> 5;
    size_t cid = blockIdx.x;
    size_t base = cid * 32;

    // ---- Phase 1: load + l2-normalize (warp per row, 8 rows/warp)
    const float4* q4 = (const float4*)q;
    const float4* k4 = (const float4*)k;
    float4* gkn4 = (float4*)g_kn;
    #pragma unroll
    for (int rr = 0; rr < 8; rr++) {
        int r = wrp * 8 + rr;
        {
            float4 kk = k4[(base + r) * 32 + lane];
            float ss = kk.x * kk.x + kk.y * kk.y + kk.z * kk.z + kk.w * kk.w;
            #pragma unroll
            for (int o = 16; o; o >>= 1) ss += __shfl_xor_sync(0xffffffffu, ss, o);
            float rn = rsqrtf(ss + 1e-6f);
            kk.x *= rn; kk.y *= rn; kk.z *= rn; kk.w *= rn;
            gkn4[(base + r) * 32 + lane] = kk;
            knT[(lane * 4 + 0) * 33 + r] = kk.x;
            knT[(lane * 4 + 1) * 33 + r] = kk.y;
            knT[(lane * 4 + 2) * 33 + r] = kk.z;
            knT[(lane * 4 + 3) * 33 + r] = kk.w;
        }
        {
            float4 qq = q4[(base + r) * 32 + lane];
            float ss = qq.x * qq.x + qq.y * qq.y + qq.z * qq.z + qq.w * qq.w;
            #pragma unroll
            for (int o = 16; o; o >>= 1) ss += __shfl_xor_sync(0xffffffffu, ss, o);
            float rn = rsqrtf(ss + 1e-6f);
            qq.x *= rn; qq.y *= rn; qq.z *= rn; qq.w *= rn;
            qnT[(lane * 4 + 0) * 33 + r] = qq.x;
            qnT[(lane * 4 + 1) * 33 + r] = qq.y;
            qnT[(lane * 4 + 2) * 33 + r] = qq.z;
            qnT[(lane * 4 + 3) * 33 + r] = qq.w;
        }
    }
    if (tid < 32) beta_s[tid] = beta[base + tid];
    __syncthreads();

    int j = lane, iw = wrp;

    // ---- Phase 2: A = -(beta_i * kn_i . kn_j), strictly lower (all warps)
    {
        float acc[8] = {0, 0, 0, 0, 0, 0, 0, 0};
        for (int d = 0; d < 128; d++) {
            float kj = knT[d * 33 + j];
            #pragma unroll
            for (int ii = 0; ii < 8; ii++)
                acc[ii] += knT[d * 33 + (iw * 8 + ii)] * kj;
        }
        #pragma unroll
        for (int ii = 0; ii < 8; ii++) {
            int i = iw * 8 + ii;
            A[i * 33 + j] = (i > j) ? (-beta_s[i] * acc[ii]) : 0.0f;
        }
    }
    __syncthreads();

    // ---- Phase 3 (overlapped): warp 0 -> forward substitution;
    //      warps 1-3 -> attn^T + q^T drain (pair-packed).
    if (wrp == 0) {
        for (int i = 1; i < 32; i++) {
            float upd = 0.0f;
            for (int t = lane + 1; t < i; t++)
                upd += A[i * 33 + t] * A[t * 33 + lane];
            __syncwarp();
            if (lane < i) A[i * 33 + lane] += upd;
            __syncwarp();
        }
    } else {
        int r0 = (wrp - 1) * 11;
        int nr = (wrp == 3) ? 10 : 11;
        float acc[11];
        #pragma unroll
        for (int ii = 0; ii < 11; ii++) acc[ii] = 0.0f;
        for (int d = 0; d < 128; d++) {
            float qv = qnT[d * 33 + lane];
            #pragma unroll
            for (int ii = 0; ii < 11; ii++)
                if (ii < nr)
                    acc[ii] += knT[d * 33 + (r0 + ii)] * qv;
        }
        float* ga = g_attn + cid * 1024;
        #pragma unroll
        for (int ii = 0; ii < 11; ii++) {
            if (ii < nr) {
                int jr = r0 + ii;
                ga[jr * 32 + lane] = (lane >= jr) ? acc[ii] : 0.0f;
            }
        }
        // q^T drain pair-packed: gq2[d2*32+c] = (q[2d2][c], q[2d2+1][c])
        ull* gq2 = (ull*)(g_qt + base * 128);
        for (int idx = tid - 32; idx < 2048; idx += 96) {
            int d2 = idx >> 5, c = idx & 31;
            gq2[idx] = pack2(qnT[(2 * d2) * 33 + c], qnT[(2 * d2 + 1) * 33 + c]);
        }
    }
    __syncthreads();

    // ---- Phase 4 (scalar, R11): u = (A+I)@(beta*v) -> g_u;
    //      w = (A+I)@(beta*kn) -> staged in knT
    {
        int d32 = lane;
        int cw  = wrp;
        float4 au[8], aw[8];
        #pragma unroll
        for (int ii = 0; ii < 8; ii++) {
            int c = cw * 8 + ii;
            float4 vv = *(const float4*)&v[(base + c) * 128 + d32 * 4];
            float4 kk = *(const float4*)&g_kn[(base + c) * 128 + d32 * 4];
            float bc = beta_s[c];
            au[ii] = make_float4(vv.x * bc, vv.y * bc, vv.z * bc, vv.w * bc);
            aw[ii] = make_float4(kk.x * bc, kk.y * bc, kk.z * bc, kk.w * bc);
        }
        for (int t = 0; t < 32; t++) {
            float bt = beta_s[t];
            float4 vv = *(const float4*)&v[(base + t) * 128 + d32 * 4];
            float4 kk = *(const float4*)&g_kn[(base + t) * 128 + d32 * 4];
            vv.x *= bt; vv.y *= bt; vv.z *= bt; vv.w *= bt;
            kk.x *= bt; kk.y *= bt; kk.z *= bt; kk.w *= bt;
            #pragma unroll
            for (int ii = 0; ii < 8; ii++) {
                float a = A[(cw * 8 + ii) * 33 + t];
                au[ii].x += a * vv.x; au[ii].y += a * vv.y;
                au[ii].z += a * vv.z; au[ii].w += a * vv.w;
                aw[ii].x += a * kk.x; aw[ii].y += a * kk.y;
                aw[ii].z += a * kk.z; aw[ii].w += a * kk.w;
            }
        }
        #pragma unroll
        for (int ii = 0; ii < 8; ii++) {
            int c = cw * 8 + ii;
            *(float4*)&g_u[(base + c) * 128 + d32 * 4] = au[ii];
            knT[(d32 * 4 + 0) * 33 + c] = aw[ii].x;
            knT[(d32 * 4 + 1) * 33 + c] = aw[ii].y;
            knT[(d32 * 4 + 2) * 33 + c] = aw[ii].z;
            knT[(d32 * 4 + 3) * 33 + c] = aw[ii].w;
        }
    }
    __syncthreads();
    {   // w drain pair-packed
        ull* gw2 = (ull*)(g_wt + base * 128);
        for (int idx = tid; idx < 2048; idx += 128) {
            int d2 = idx >> 5, c = idx & 31;
            gw2[idx] = pack2(knT[(2 * d2) * 33 + c], knT[(2 * d2 + 1) * 33 + c]);
        }
    }
}

// ---------------------------------------------------------------------------
// cp.async helpers
// ---------------------------------------------------------------------------
__device__ __forceinline__ void cpa16(float* s, const void* g) {
    unsigned a = (unsigned)__cvta_generic_to_shared(s);
    asm volatile("cp.async.cg.shared.global [%0], [%1], 16;" :: "r"(a), "l"(g));
}
__device__ __forceinline__ void cpa_commit() {
    asm volatile("cp.async.commit_group;");
}
__device__ __forceinline__ void cpa_wait_all() {
    asm volatile("cp.async.wait_group 0;");
}

// Scan smem layout (floats):
//   S2 (ull[2][2048])  @ 0      (8192 floats)
//   us (float[2][1024])@ 8192
//   kw buffers x2      @ 10240  (per buf 8192: k @ +0, w @ +4096)
//   qa buffers x2      @ 26624  (per buf 5120: q @ +0, attn @ +4096)
#define SM_S2   0
#define SM_US   8192
#define SM_KW   10240
#define SM_QA   26624
#define SM_TOT  36864

// ---------------------------------------------------------------------------
// Kernel 2: decoupled scan. grid (NSPLIT, BH), 256 threads.
// Warps 0-3 (S-warps): recurrence (w@S -> us -> S += k^T u), 8 c / 32 d each.
// Warps 4-7 (O-warps): output of chunk ch-1 (q@S_prev + attn@u_prev), one
// iteration behind, off the critical path. S2 and us double-buffered.
// ---------------------------------------------------------------------------
__global__ void __launch_bounds__(256, 1) scan_kernel(float* __restrict__ out) {
    extern __shared__ float sm[];
    ull*   S2base = (ull*)sm;
    float* usbase = sm + SM_US;

    int tid = threadIdx.x;
    int bh = blockIdx.y;
    int dvoff = blockIdx.x * 32;
    int j = tid & 31;
    int wid = tid >> 5;

    const float4* gq4 = (const float4*)(g_qt + (size_t)bh * LSEQ * D);
    const float4* gk4 = (const float4*)(g_kn + (size_t)bh * LSEQ * D);
    const float4* gw4 = (const float4*)(g_wt + (size_t)bh * LSEQ * D);
    const float4* ga4 = (const float4*)(g_attn + (size_t)bh * NCHUNK * 1024);
    const float*  gu  = g_u + (size_t)bh * LSEQ * D;
    float* gout = out + (size_t)bh * LSEQ * D + dvoff;

    // S entering chunk 0 = zeros, in S2 buffer 0
    for (int i = tid; i < 2048; i += 256) S2base[i] = 0ull;

    // prefetch k/w for chunk 0 into kw buffer 0
    {
        float* KW = sm + SM_KW;
        for (int i = tid; i < 1024; i += 256) {
            cpa16(KW + 4 * i, gk4 + i);
            cpa16(KW + 4096 + 4 * i, gw4 + i);
        }
        cpa_commit();
    }

    // S-warp register-resident S rows: SP[p] = S pair (s*32+2p, s*32+2p+1) at col j
    ull SP[16];
    #pragma unroll
    for (int p = 0; p < 16; p++) SP[p] = 0ull;

    for (int ch = 0; ch <= NCHUNK; ch++) {
        cpa_wait_all();
        __syncthreads();   // staged data ready; prev S2 writes visible

        int b = ch & 1;
        float* KW   = sm + SM_KW + b * 8192;
        float* QAp  = sm + SM_QA + ((b ^ 1)) * 5120;  // qa of chunk ch-1
        ull* S2cur  = S2base + b * 2048;              // S entering ch
        ull* S2oth  = S2base + (b ^ 1) * 2048;        // S entering ch-1 -> becomes S entering ch+1
        float* usb  = usbase + b * 1024;              // us[ch]
        float* usp  = usbase + (b ^ 1) * 1024;        // us[ch-1]

        // ---- prefetch: k/w for ch+1; q/attn for ch (needed by O-warps at ch+1)
        if (ch + 1 < NCHUNK) {
            float* P = sm + SM_KW + (b ^ 1) * 8192;
            size_t off4 = (size_t)(ch + 1) * 1024;
            for (int i = tid; i < 1024; i += 256) {
                cpa16(P + 4 * i, gk4 + off4 + i);
                cpa16(P + 4096 + 4 * i, gw4 + off4 + i);
            }
        }
        if (ch < NCHUNK) {
            float* P = sm + SM_QA + b * 5120;
            size_t off4 = (size_t)ch * 1024;
            for (int i = tid; i < 1024; i += 256)
                cpa16(P + 4 * i, gq4 + off4 + i);
            cpa16(P + 4096 + 4 * tid, ga4 + (size_t)ch * 256 + tid);
        }
        cpa_commit();

        ull OP[4];   // O-warp output pairs, carried into phase 2

        if (wid < 4) {
            // ================= S-warps, phase 1: MW = w@S, us =================
            if (ch < NCHUNK) {
                int s = wid;
                float u0v[8];
                #pragma unroll
                for (int i = 0; i < 8; i++)
                    u0v[i] = gu[(size_t)(ch * 32 + s * 8 + i) * 128 + dvoff + j];
                ull MW[8];
                #pragma unroll
                for (int i = 0; i < 8; i++) MW[i] = 0ull;
                const ull* wull = (const ull*)(KW + 4096);
                #pragma unroll 2
                for (int d2 = 0; d2 < 64; d2++) {
                    ull sv = S2cur[d2 * 32 + j];
                    const ulonglong2* wp = (const ulonglong2*)(wull + d2 * 32 + s * 8);
                    ulonglong2 w0 = wp[0], w1 = wp[1], w2 = wp[2], w3 = wp[3];
                    fma2(MW[0], w0.x, sv); fma2(MW[1], w0.y, sv);
                    fma2(MW[2], w1.x, sv); fma2(MW[3], w1.y, sv);
                    fma2(MW[4], w2.x, sv); fma2(MW[5], w2.y, sv);
                    fma2(MW[6], w3.x, sv); fma2(MW[7], w3.y, sv);
                }
                #pragma unroll
                for (int i = 0; i < 8; i++)
                    usb[(s * 8 + i) * 32 + j] = u0v[i] - hadd2(MW[i]);
            }
        } else {
            // ================= O-warps, phase 1: O = q@S_prev ================
            if (ch >= 1) {
                int o = wid - 4;
                ull O[8];
                #pragma unroll
                for (int i = 0; i < 8; i++) O[i] = 0ull;
                const ull* qull = (const ull*)QAp;
                #pragma unroll 2
                for (int d2 = 0; d2 < 64; d2++) {
                    ull sv = S2oth[d2 * 32 + j];   // S entering ch-1
                    const ulonglong2* qp = (const ulonglong2*)(qull + d2 * 32 + o * 8);
                    ulonglong2 q0 = qp[0], q1 = qp[1], q2 = qp[2], q3 = qp[3];
                    fma2(O[0], q0.x, sv); fma2(O[1], q0.y, sv);
                    fma2(O[2], q1.x, sv); fma2(O[3], q1.y, sv);
                    fma2(O[4], q2.x, sv); fma2(O[5], q2.y, sv);
                    fma2(O[6], q3.x, sv); fma2(O[7], q3.y, sv);
                }
                OP[0] = pack2(hadd2(O[0]), hadd2(O[1]));
                OP[1] = pack2(hadd2(O[2]), hadd2(O[3]));
                OP[2] = pack2(hadd2(O[4]), hadd2(O[5]));
                OP[3] = pack2(hadd2(O[6]), hadd2(O[7]));
            }
        }
        __syncthreads();   // us[ch] ready; O-warps done reading S2oth

        if (wid < 4) {
            // ============ S-warps, phase 2: S += k^T u -> S2oth ============
            if (ch < NCHUNK) {
                int s = wid;
                const ulonglong2* kk2 = (const ulonglong2*)KW;
                #pragma unroll 2
                for (int c = 0; c < 32; c++) {
                    ull ud = packdup(usb[c * 32 + j]);
                    ulonglong2 kv0 = kk2[c * 32 + s * 8 + 0];
                    ulonglong2 kv1 = kk2[c * 32 + s * 8 + 1];
                    ulonglong2 kv2 = kk2[c * 32 + s * 8 + 2];
                    ulonglong2 kv3 = kk2[c * 32 + s * 8 + 3];
                    ulonglong2 kv4 = kk2[c * 32 + s * 8 + 4];
                    ulonglong2 kv5 = kk2[c * 32 + s * 8 + 5];
                    ulonglong2 kv6 = kk2[c * 32 + s * 8 + 6];
                    ulonglong2 kv7 = kk2[c * 32 + s * 8 + 7];
                    fma2(SP[0],  kv0.x, ud); fma2(SP[1],  kv0.y, ud);
                    fma2(SP[2],  kv1.x, ud); fma2(SP[3],  kv1.y, ud);
                    fma2(SP[4],  kv2.x, ud); fma2(SP[5],  kv2.y, ud);
                    fma2(SP[6],  kv3.x, ud); fma2(SP[7],  kv3.y, ud);
                    fma2(SP[8],  kv4.x, ud); fma2(SP[9],  kv4.y, ud);
                    fma2(SP[10], kv5.x, ud); fma2(SP[11], kv5.y, ud);
                    fma2(SP[12], kv6.x, ud); fma2(SP[13], kv6.y, ud);
                    fma2(SP[14], kv7.x, ud); fma2(SP[15], kv7.y, ud);
                }
                // S entering ch+1 -> S2oth (warp-disjoint rows)
                #pragma unroll
                for (int p = 0; p < 16; p++)
                    S2oth[(s * 16 + p) * 32 + j] = SP[p];
            }
        } else {
            // ====== O-warps, phase 2: O += attn@u_prev ; store out[ch-1] ======
            if (ch >= 1) {
                int o = wid - 4;
                const ulonglong2* aull2 = (const ulonglong2*)(QAp + 4096);
                #pragma unroll 2
                for (int t = 0; t < 32; t++) {
                    ull ud = packdup(usp[t * 32 + j]);
                    ulonglong2 a0 = aull2[t * 8 + o * 2];
                    ulonglong2 a1 = aull2[t * 8 + o * 2 + 1];
                    fma2(OP[0], a0.x, ud); fma2(OP[1], a0.y, ud);
                    fma2(OP[2], a1.x, ud); fma2(OP[3], a1.y, ud);
                }
                int och = ch - 1;
                #pragma unroll
                for (int p = 0; p < 4; p++) {
                    float oa, ob;
                    unpack2(OP[p], oa, ob);
                    gout[(size_t)(och * 32 + o * 8 + 2 * p) * 128 + j]     = oa;
                    gout[(size_t)(och * 32 + o * 8 + 2 * p + 1) * 128 + j] = ob;
                }
            }
        }
        // next iteration's top barrier orders S2oth writes before all reads
    }
}

// ---------------------------------------------------------------------------
extern "C" void kernel_launch(void* const* d_in, const int* in_sizes, int n_in,
                              void* d_out, int out_size) {
    const float* q    = (const float*)d_in[0];
    const float* k    = (const float*)d_in[1];
    const float* v    = (const float*)d_in[2];
    const float* beta = (const float*)d_in[3];
    float* out = (float*)d_out;

    chunk_kernel<<<BH * NCHUNK, 128>>>(q, k, v, beta);

    const int smem_bytes = SM_TOT * sizeof(float);   // 144 KB
    cudaFuncSetAttribute(scan_kernel,
                         cudaFuncAttributeMaxDynamicSharedMemorySize, smem_bytes);
    scan_kernel<<<dim3(NSPLIT, BH), 256, smem_bytes>>>(out);
}

// round 14
// speedup vs baseline: 1.0060x; 1.0060x over previous
#include <cuda_runtime.h>

#define BH     32
#define LSEQ   4096
#define D      128
#define C      32
#define NCHUNK 128
#define NSPLIT 4

typedef unsigned long long ull;

// Scratch (device globals are the allowed scratch mechanism)
// g_qt / g_wt are d-pair-interleaved ull arrays: ull idx = chunkbase*64 + d2*32 + c
//   value = ( {q,w}[2*d2][c] , {q,w}[2*d2+1][c] )
__device__ __align__(16) float g_qt[(size_t)BH * LSEQ * D];
__device__ __align__(16) float g_kn[(size_t)BH * LSEQ * D];   // row-major normalized k
__device__ __align__(16) float g_u [(size_t)BH * LSEQ * D];   // u0 (row-major)
__device__ __align__(16) float g_wt[(size_t)BH * LSEQ * D];
__device__ __align__(16) float g_attn[(size_t)BH * NCHUNK * C * C];  // attn^T: [t][c]

// ---------------------------------------------------------------------------
// f32x2 packed helpers
// ---------------------------------------------------------------------------
__device__ __forceinline__ void fma2(ull& acc, ull a, ull b) {
    asm("fma.rn.f32x2 %0, %1, %2, %0;" : "+l"(acc) : "l"(a), "l"(b));
}
__device__ __forceinline__ void mul2(ull& d, ull a, ull b) {
    asm("mul.rn.f32x2 %0, %1, %2;" : "=l"(d) : "l"(a), "l"(b));
}
__device__ __forceinline__ ull packdup(float s) {
    ull r;
    asm("mov.b64 %0, {%1, %1};" : "=l"(r) : "r"(__float_as_uint(s)));
    return r;
}
__device__ __forceinline__ ull pack2(float lo, float hi) {
    ull r;
    asm("mov.b64 %0, {%1, %2};" : "=l"(r) : "r"(__float_as_uint(lo)), "r"(__float_as_uint(hi)));
    return r;
}
__device__ __forceinline__ void unpack2(ull v, float& lo, float& hi) {
    unsigned a, b;
    asm("mov.b64 {%0, %1}, %2;" : "=r"(a), "=r"(b) : "l"(v));
    lo = __uint_as_float(a); hi = __uint_as_float(b);
}
__device__ __forceinline__ float hadd2(ull v) {
    float lo, hi; unpack2(v, lo, hi); return lo + hi;
}

// ---------------------------------------------------------------------------
// Kernel 1 (fused norm + chunk). 4096 blocks, 128 threads.
// f32x2 phases 2 / attn (paired over adjacent accumulator rows; stride-34 smem
// keeps ull alignment) and phase 4 (inline packdup of A — NO extra smem).
// ---------------------------------------------------------------------------
__global__ void chunk_kernel(const float* __restrict__ q,
                             const float* __restrict__ k,
                             const float* __restrict__ v,
                             const float* __restrict__ beta) {
    __shared__ float knT[128 * 34];   // k^T (normalized); stride 34 (even -> ull-aligned rows)
    __shared__ float qnT[128 * 34];   // q^T (normalized)
    __shared__ float A[32 * 33];
    __shared__ ull   beta2[32];
    __shared__ float beta_s[32];

    int tid = threadIdx.x;
    int lane = tid & 31, wrp = tid >> 5;
    size_t cid = blockIdx.x;
    size_t base = cid * 32;

    // ---- Phase 1: load + l2-normalize (warp per row, 8 rows/warp)
    const float4* q4 = (const float4*)q;
    const float4* k4 = (const float4*)k;
    float4* gkn4 = (float4*)g_kn;
    #pragma unroll
    for (int rr = 0; rr < 8; rr++) {
        int r = wrp * 8 + rr;
        {
            float4 kk = k4[(base + r) * 32 + lane];
            float ss = kk.x * kk.x + kk.y * kk.y + kk.z * kk.z + kk.w * kk.w;
            #pragma unroll
            for (int o = 16; o; o >>= 1) ss += __shfl_xor_sync(0xffffffffu, ss, o);
            float rn = rsqrtf(ss + 1e-6f);
            kk.x *= rn; kk.y *= rn; kk.z *= rn; kk.w *= rn;
            gkn4[(base + r) * 32 + lane] = kk;
            knT[(lane * 4 + 0) * 34 + r] = kk.x;
            knT[(lane * 4 + 1) * 34 + r] = kk.y;
            knT[(lane * 4 + 2) * 34 + r] = kk.z;
            knT[(lane * 4 + 3) * 34 + r] = kk.w;
        }
        {
            float4 qq = q4[(base + r) * 32 + lane];
            float ss = qq.x * qq.x + qq.y * qq.y + qq.z * qq.z + qq.w * qq.w;
            #pragma unroll
            for (int o = 16; o; o >>= 1) ss += __shfl_xor_sync(0xffffffffu, ss, o);
            float rn = rsqrtf(ss + 1e-6f);
            qq.x *= rn; qq.y *= rn; qq.z *= rn; qq.w *= rn;
            qnT[(lane * 4 + 0) * 34 + r] = qq.x;
            qnT[(lane * 4 + 1) * 34 + r] = qq.y;
            qnT[(lane * 4 + 2) * 34 + r] = qq.z;
            qnT[(lane * 4 + 3) * 34 + r] = qq.w;
        }
    }
    if (tid < 32) {
        float b = beta[base + tid];
        beta_s[tid] = b;
        beta2[tid] = packdup(b);
    }
    __syncthreads();

    int j = lane, iw = wrp;

    // ---- Phase 2 (f32x2, i-paired): A = -(beta_i * kn_i . kn_j), strictly lower
    {
        ull acc2[4] = {0ull, 0ull, 0ull, 0ull};
        for (int d = 0; d < 128; d++) {
            ull kj = packdup(knT[d * 34 + j]);                   // lane-varying
            const ull* rowp = (const ull*)(knT + d * 34 + iw * 8); // (i,i+1) pairs, broadcast
            #pragma unroll
            for (int p = 0; p < 4; p++)
                fma2(acc2[p], rowp[p], kj);
        }
        #pragma unroll
        for (int p = 0; p < 4; p++) {
            float a0, a1;
            unpack2(acc2[p], a0, a1);
            int i0 = iw * 8 + 2 * p, i1 = i0 + 1;
            A[i0 * 33 + j] = (i0 > j) ? (-beta_s[i0] * a0) : 0.0f;
            A[i1 * 33 + j] = (i1 > j) ? (-beta_s[i1] * a1) : 0.0f;
        }
    }
    __syncthreads();

    // ---- Phase 3 (overlapped): warp 0 -> forward substitution;
    //      warps 1-3 -> attn^T (f32x2, rows 12/12/8) + q^T drain (pair-packed).
    if (wrp == 0) {
        for (int i = 1; i < 32; i++) {
            float upd = 0.0f;
            for (int t = lane + 1; t < i; t++)
                upd += A[i * 33 + t] * A[t * 33 + lane];
            __syncwarp();
            if (lane < i) A[i * 33 + lane] += upd;
            __syncwarp();
        }
    } else {
        int r0 = (wrp - 1) * 12;              // rows r0 .. r0+nr-1
        int np = (wrp == 3) ? 4 : 6;          // row-pairs
        ull acc2[6] = {0ull, 0ull, 0ull, 0ull, 0ull, 0ull};
        for (int d = 0; d < 128; d++) {
            ull qv = packdup(qnT[d * 34 + lane]);
            const ull* rowp = (const ull*)(knT + d * 34 + r0);
            #pragma unroll
            for (int p = 0; p < 6; p++)
                if (p < np) fma2(acc2[p], rowp[p], qv);
        }
        float* ga = g_attn + cid * 1024;
        #pragma unroll
        for (int p = 0; p < 6; p++) {
            if (p < np) {
                float a0, a1;
                unpack2(acc2[p], a0, a1);
                int jr0 = r0 + 2 * p, jr1 = jr0 + 1;
                ga[jr0 * 32 + lane] = (lane >= jr0) ? a0 : 0.0f;
                ga[jr1 * 32 + lane] = (lane >= jr1) ? a1 : 0.0f;
            }
        }
        // q^T drain pair-packed: gq2[d2*32+c] = (q[2d2][c], q[2d2+1][c])
        ull* gq2 = (ull*)(g_qt + base * 128);
        for (int idx = tid - 32; idx < 2048; idx += 96) {
            int d2 = idx >> 5, c = idx & 31;
            gq2[idx] = pack2(qnT[(2 * d2) * 34 + c], qnT[(2 * d2 + 1) * 34 + c]);
        }
    }
    __syncthreads();

    // ---- Phase 4 (f32x2, inline A dup): u = (A+I)@(beta*v) -> g_u;
    //      w = (A+I)@(beta*kn) -> staged in knT (stride 34)
    {
        int d32 = lane;                 // d pairs: (4*lane,4*lane+1),(4*lane+2,4*lane+3)
        int cw  = wrp;
        const ulonglong2* v2  = (const ulonglong2*)v;
        const ulonglong2* kn2 = (const ulonglong2*)g_kn;
        ull au0[8], au1[8], aw0[8], aw1[8];
        #pragma unroll
        for (int ii = 0; ii < 8; ii++) {
            int c = cw * 8 + ii;
            ulonglong2 vv = v2[(base + c) * 32 + d32];
            ulonglong2 kk = kn2[(base + c) * 32 + d32];
            ull b2 = beta2[c];
            mul2(au0[ii], vv.x, b2); mul2(au1[ii], vv.y, b2);
            mul2(aw0[ii], kk.x, b2); mul2(aw1[ii], kk.y, b2);
        }
        for (int t = 0; t < 32; t++) {
            ulonglong2 vv = v2[(base + t) * 32 + d32];
            ulonglong2 kk = kn2[(base + t) * 32 + d32];
            ull b2 = beta2[t];
            ull vb0, vb1, kb0, kb1;
            mul2(vb0, vv.x, b2); mul2(vb1, vv.y, b2);
            mul2(kb0, kk.x, b2); mul2(kb1, kk.y, b2);
            #pragma unroll
            for (int ii = 0; ii < 8; ii++) {
                ull a2 = packdup(A[(cw * 8 + ii) * 33 + t]);   // inline dup, no A2s array
                fma2(au0[ii], a2, vb0); fma2(au1[ii], a2, vb1);
                fma2(aw0[ii], a2, kb0); fma2(aw1[ii], a2, kb1);
            }
        }
        ulonglong2* gu2 = (ulonglong2*)g_u;
        #pragma unroll
        for (int ii = 0; ii < 8; ii++) {
            int c = cw * 8 + ii;
            ulonglong2 st; st.x = au0[ii]; st.y = au1[ii];
            gu2[(base + c) * 32 + d32] = st;
            float x, y, z, w2;
            unpack2(aw0[ii], x, y);
            unpack2(aw1[ii], z, w2);
            knT[(d32 * 4 + 0) * 34 + c] = x;
            knT[(d32 * 4 + 1) * 34 + c] = y;
            knT[(d32 * 4 + 2) * 34 + c] = z;
            knT[(d32 * 4 + 3) * 34 + c] = w2;
        }
    }
    __syncthreads();
    {   // w drain pair-packed
        ull* gw2 = (ull*)(g_wt + base * 128);
        for (int idx = tid; idx < 2048; idx += 128) {
            int d2 = idx >> 5, c = idx & 31;
            gw2[idx] = pack2(knT[(2 * d2) * 34 + c], knT[(2 * d2 + 1) * 34 + c]);
        }
    }
}

// ---------------------------------------------------------------------------
// cp.async helpers
// ---------------------------------------------------------------------------
__device__ __forceinline__ void cpa16(float* s, const void* g) {
    unsigned a = (unsigned)__cvta_generic_to_shared(s);
    asm volatile("cp.async.cg.shared.global [%0], [%1], 16;" :: "r"(a), "l"(g));
}
__device__ __forceinline__ void cpa_commit() {
    asm volatile("cp.async.commit_group;");
}
__device__ __forceinline__ void cpa_wait_all() {
    asm volatile("cp.async.wait_group 0;");
}

// Scan buffer layout (floats, per buffer):
//   qP[4096] @0, k[4096] @4096, wP[4096] @8192, attnT[1024] @12288
#define OFF_Q    0
#define OFF_K    4096
#define OFF_W    8192
#define OFF_A    12288
#define BUF_FLOATS 13312

// ---------------------------------------------------------------------------
// Kernel 2: sequential scan — R12 version verbatim (best measured: 571.6 us).
// S pair-interleaved in smem; warp-owned rows register-resident; fused w@S/q@S
// loop with lane-varying LDS.64 S operands; attn@u merged into S-update c-loop.
// ---------------------------------------------------------------------------
__global__ void __launch_bounds__(256, 1) scan_kernel(float* __restrict__ out) {
    extern __shared__ float sm[];
    ull*   S2 = (ull*)sm;                       // [d2=64][j=32] pairs (16 KB)
    float* us = sm + 4096 + 2 * BUF_FLOATS;     // [c=32][j=32]

    int tid = threadIdx.x;
    int bh = blockIdx.y;
    int dvoff = blockIdx.x * 32;
    int j = tid & 31;
    int cg = tid >> 5;

    const float4* gq4 = (const float4*)(g_qt + (size_t)bh * LSEQ * D);
    const float4* gk4 = (const float4*)(g_kn + (size_t)bh * LSEQ * D);
    const float4* gw4 = (const float4*)(g_wt + (size_t)bh * LSEQ * D);
    const float4* ga4 = (const float4*)(g_attn + (size_t)bh * NCHUNK * 1024);
    const float*  gu  = g_u + (size_t)bh * LSEQ * D;
    float* gout = out + (size_t)bh * LSEQ * D + dvoff;

    {
        float* B = sm + 4096;
        for (int i = tid; i < 1024; i += 256) {
            cpa16(B + OFF_Q + 4 * i, gq4 + i);
            cpa16(B + OFF_K + 4 * i, gk4 + i);
            cpa16(B + OFF_W + 4 * i, gw4 + i);
        }
        cpa16(B + OFF_A + 4 * tid, ga4 + tid);
        cpa_commit();
    }

    for (int i = tid; i < 2048; i += 256) S2[i] = 0ull;

    ull SP[8];
    #pragma unroll
    for (int p = 0; p < 8; p++) SP[p] = 0ull;

    for (int ch = 0; ch < NCHUNK; ch++) {
        cpa_wait_all();
        __syncthreads();

        float* B = sm + 4096 + (ch & 1) * BUF_FLOATS;
        const ulonglong2* qP2 = (const ulonglong2*)(B + OFF_Q);
        const ulonglong2* kk2 = (const ulonglong2*)(B + OFF_K);
        const ulonglong2* wP2 = (const ulonglong2*)(B + OFF_W);
        const ulonglong2* aT2 = (const ulonglong2*)(B + OFF_A);

        float u00 = gu[(size_t)(ch * 32 + cg * 4 + 0) * 128 + dvoff + j];
        float u01 = gu[(size_t)(ch * 32 + cg * 4 + 1) * 128 + dvoff + j];
        float u02 = gu[(size_t)(ch * 32 + cg * 4 + 2) * 128 + dvoff + j];
        float u03 = gu[(size_t)(ch * 32 + cg * 4 + 3) * 128 + dvoff + j];

        if (ch + 1 < NCHUNK) {
            float* P = sm + 4096 + ((ch + 1) & 1) * BUF_FLOATS;
            size_t off4 = (size_t)(ch + 1) * 1024;
            for (int i = tid; i < 1024; i += 256) {
                cpa16(P + OFF_Q + 4 * i, gq4 + off4 + i);
                cpa16(P + OFF_K + 4 * i, gk4 + off4 + i);
                cpa16(P + OFF_W + 4 * i, gw4 + off4 + i);
            }
            cpa16(P + OFF_A + 4 * tid, ga4 + (size_t)(ch + 1) * 256 + tid);
            cpa_commit();
        }

        // ---- fused: MW = w@S, O = q@S, accumulated as (even-d, odd-d) pairs
        ull MW0 = 0, MW1 = 0, MW2 = 0, MW3 = 0;
        ull Oa = 0, Ob = 0, Oc = 0, Od = 0;
        #pragma unroll 4
        for (int d2 = 0; d2 < 64; d2++) {
            ull sv = S2[d2 * 32 + j];
            ulonglong2 wA = wP2[d2 * 16 + cg * 2];
            ulonglong2 wB = wP2[d2 * 16 + cg * 2 + 1];
            ulonglong2 qA = qP2[d2 * 16 + cg * 2];
            ulonglong2 qB = qP2[d2 * 16 + cg * 2 + 1];
            fma2(MW0, wA.x, sv); fma2(MW1, wA.y, sv);
            fma2(MW2, wB.x, sv); fma2(MW3, wB.y, sv);
            fma2(Oa, qA.x, sv);  fma2(Ob, qA.y, sv);
            fma2(Oc, qB.x, sv);  fma2(Od, qB.y, sv);
        }
        float uc0 = u00 - hadd2(MW0);
        float uc1 = u01 - hadd2(MW1);
        float uc2 = u02 - hadd2(MW2);
        float uc3 = u03 - hadd2(MW3);
        us[(cg * 4 + 0) * 32 + j] = uc0;
        us[(cg * 4 + 1) * 32 + j] = uc1;
        us[(cg * 4 + 2) * 32 + j] = uc2;
        us[(cg * 4 + 3) * 32 + j] = uc3;
        ull O01 = pack2(hadd2(Oa), hadd2(Ob));
        ull O23 = pack2(hadd2(Oc), hadd2(Od));
        __syncthreads();

        // ---- merged c-loop: O += attn^T u  AND  SP += k^T u
        #pragma unroll 2
        for (int c = 0; c < 32; c++) {
            ull ud = packdup(us[c * 32 + j]);
            ulonglong2 av = aT2[c * 8 + cg];
            fma2(O01, av.x, ud);
            fma2(O23, av.y, ud);
            #pragma unroll
            for (int qq = 0; qq < 4; qq++) {
                ulonglong2 kv = kk2[c * 32 + cg * 4 + qq];
                fma2(SP[2 * qq + 0], kv.x, ud);
                fma2(SP[2 * qq + 1], kv.y, ud);
            }
        }
        {
            float o0, o1, o2, o3;
            unpack2(O01, o0, o1);
            unpack2(O23, o2, o3);
            gout[(size_t)(ch * 32 + cg * 4 + 0) * 128 + j] = o0;
            gout[(size_t)(ch * 32 + cg * 4 + 1) * 128 + j] = o1;
            gout[(size_t)(ch * 32 + cg * 4 + 2) * 128 + j] = o2;
            gout[(size_t)(ch * 32 + cg * 4 + 3) * 128 + j] = o3;
        }
        #pragma unroll
        for (int p = 0; p < 8; p++)
            S2[(cg * 8 + p) * 32 + j] = SP[p];
    }
}

// ---------------------------------------------------------------------------
extern "C" void kernel_launch(void* const* d_in, const int* in_sizes, int n_in,
                              void* d_out, int out_size) {
    const float* q    = (const float*)d_in[0];
    const float* k    = (const float*)d_in[1];
    const float* v    = (const float*)d_in[2];
    const float* beta = (const float*)d_in[3];
    float* out = (float*)d_out;

    chunk_kernel<<<BH * NCHUNK, 128>>>(q, k, v, beta);

    const int smem_bytes = (4096 + 2 * BUF_FLOATS + 1024) * sizeof(float); // ~124 KB
    cudaFuncSetAttribute(scan_kernel,
                         cudaFuncAttributeMaxDynamicSharedMemorySize, smem_bytes);
    scan_kernel<<<dim3(NSPLIT, BH), 256, smem_bytes>>>(out);
}